// round 6
// baseline (speedup 1.0000x reference)
#include <cuda_runtime.h>
#include <math.h>

#define BATCH 16384
#define DIM 4096
#define NUM_EXPERTS 64
#define TOP_K 2

// Output layout: [expanded_x (32768*4096) | indices (32768) | weights (32768)]

__device__ __forceinline__ bool better(float v, int i, float w, int j) {
    return (v > w) || (v == w && i < j);
}

// 32768 blocks x 256 threads. Each thread copies TWO float4s of its token row
// (cols c and c+256) to both replicated output rows: 2 loads, 4 stores.
// Warp 0 of every 2nd block also computes the router top-2 for its row.
__global__ void __launch_bounds__(256) fused_dispatch_kernel(
    const float4* __restrict__ x,
    const float* __restrict__ logits,
    float4* __restrict__ out,
    float* __restrict__ idx_out,
    float* __restrict__ w_out) {

    // each block covers 512 f4 (cols [half*512 .. half*512+511] via two 256-chunks)
    const unsigned token = blockIdx.x >> 1;          // 2 blocks per row
    const unsigned half  = blockIdx.x & 1u;          // which half of the row
    const unsigned c0    = half * 512u + threadIdx.x;    // first col
    const unsigned c1    = c0 + 256u;                    // second col

    const bool is_router = (half == 0u) && (threadIdx.x < 32u);
    const int  lane = threadIdx.x;

    const size_t in_base = (size_t)token * 1024;
    // issue all loads up front
    float4 va = __ldcs(&x[in_base + c0]);
    float4 vb = __ldcs(&x[in_base + c1]);
    float l0 = 0.0f, l1 = 0.0f;
    if (is_router) {
        const float* l = logits + (size_t)token * NUM_EXPERTS;
        l0 = l[lane];
        l1 = l[lane + 32];
    }

    const size_t ob = (size_t)token * 2048;  // 2 output rows of 1024 f4
    __stcs(&out[ob + c0],        va);
    __stcs(&out[ob + c1],        vb);
    __stcs(&out[ob + 1024 + c0], va);
    __stcs(&out[ob + 1024 + c1], vb);

    if (is_router) {
        float a, b; int ai, bi;
        if (better(l0, lane, l1, lane + 32)) { a = l0; ai = lane;      b = l1; bi = lane + 32; }
        else                                 { a = l1; ai = lane + 32; b = l0; bi = lane; }

        #pragma unroll
        for (int off = 16; off > 0; off >>= 1) {
            float oa = __shfl_xor_sync(0xffffffffu, a, off);
            int  oai = __shfl_xor_sync(0xffffffffu, ai, off);
            float ob2 = __shfl_xor_sync(0xffffffffu, b, off);
            int  obi = __shfl_xor_sync(0xffffffffu, bi, off);

            float na, nb; int nai, nbi;
            if (better(a, ai, oa, oai)) {
                na = a; nai = ai;
                if (better(b, bi, oa, oai)) { nb = b;   nbi = bi; }
                else                        { nb = oa;  nbi = oai; }
            } else {
                na = oa; nai = oai;
                if (better(a, ai, ob2, obi)) { nb = a;   nbi = ai; }
                else                         { nb = ob2; nbi = obi; }
            }
            a = na; ai = nai; b = nb; bi = nbi;
        }

        if (lane == 0) {
            // renormalized top-2 softmax: exp(a)/(exp(a)+exp(b)), exp(b)/(...)
            float e = __expf(b - a);          // <= 1, safe
            float inv = 1.0f / (1.0f + e);
            const int row = (int)token;
            idx_out[row * 2 + 0] = (float)ai;
            idx_out[row * 2 + 1] = (float)bi;
            w_out[row * 2 + 0] = inv;
            w_out[row * 2 + 1] = e * inv;
        }
    }
}

extern "C" void kernel_launch(void* const* d_in, const int* in_sizes, int n_in,
                              void* d_out, int out_size) {
    const float* x      = (const float*)d_in[0];  // [16384, 4096]
    const float* logits = (const float*)d_in[1];  // [16384, 64]
    float* out = (float*)d_out;

    const size_t expanded_elems = (size_t)BATCH * TOP_K * DIM;
    float* idx_out = out + expanded_elems;
    float* w_out   = idx_out + (size_t)BATCH * TOP_K;

    const unsigned blocks = BATCH * 2;   // 32768 blocks, 2 per token row
    fused_dispatch_kernel<<<blocks, 256>>>((const float4*)x, logits,
                                           (float4*)out, idx_out, w_out);
}

// round 7
// speedup vs baseline: 1.0117x; 1.0117x over previous
#include <cuda_runtime.h>
#include <math.h>

#define BATCH 16384
#define DIM 4096
#define NUM_EXPERTS 64
#define TOP_K 2

// Output layout: [expanded_x (32768*4096) | indices (32768) | weights (32768)]

__device__ __forceinline__ bool better(float v, int i, float w, int j) {
    return (v > w) || (v == w && i < j);
}

// 65536 blocks x 256 threads. Each thread copies one float4 of x to both
// replicated output rows (plain loads/stores — no cache hints).
// Warp 0 of every 4th block also computes the router top-2 for its row.
__global__ void __launch_bounds__(256) fused_dispatch_kernel(
    const float4* __restrict__ x,
    const float* __restrict__ logits,
    float4* __restrict__ out,
    float* __restrict__ idx_out,
    float* __restrict__ w_out) {

    const unsigned i = blockIdx.x * 256u + threadIdx.x;
    const unsigned token = i >> 10;          // / 1024 f4 per input row
    const unsigned col   = i & 1023;

    const bool is_router = ((blockIdx.x & 3u) == 0u) && (threadIdx.x < 32u);
    const int  lane = threadIdx.x;

    // issue all loads up front
    float4 v = x[i];
    float l0 = 0.0f, l1 = 0.0f;
    if (is_router) {
        const float* l = logits + (size_t)(blockIdx.x >> 2) * NUM_EXPERTS;
        l0 = l[lane];
        l1 = l[lane + 32];
    }

    const size_t base = (size_t)token * 2048 + col;  // 2 output rows of 1024 f4
    out[base]        = v;
    out[base + 1024] = v;

    if (is_router) {
        const int row = blockIdx.x >> 2;
        float a, b; int ai, bi;
        if (better(l0, lane, l1, lane + 32)) { a = l0; ai = lane;      b = l1; bi = lane + 32; }
        else                                 { a = l1; ai = lane + 32; b = l0; bi = lane; }

        #pragma unroll
        for (int off = 16; off > 0; off >>= 1) {
            float oa = __shfl_xor_sync(0xffffffffu, a, off);
            int  oai = __shfl_xor_sync(0xffffffffu, ai, off);
            float ob = __shfl_xor_sync(0xffffffffu, b, off);
            int  obi = __shfl_xor_sync(0xffffffffu, bi, off);

            float na, nb; int nai, nbi;
            if (better(a, ai, oa, oai)) {
                na = a; nai = ai;
                if (better(b, bi, oa, oai)) { nb = b;  nbi = bi; }
                else                        { nb = oa; nbi = oai; }
            } else {
                na = oa; nai = oai;
                if (better(a, ai, ob, obi)) { nb = a;  nbi = ai; }
                else                        { nb = ob; nbi = obi; }
            }
            a = na; ai = nai; b = nb; bi = nbi;
        }

        if (lane == 0) {
            // renormalized top-2 softmax: exp(a)/(exp(a)+exp(b)), exp(b)/(...)
            float e = __expf(b - a);          // <= 1, safe
            float inv = 1.0f / (1.0f + e);
            idx_out[row * 2 + 0] = (float)ai;
            idx_out[row * 2 + 1] = (float)bi;
            w_out[row * 2 + 0] = inv;
            w_out[row * 2 + 1] = e * inv;
        }
    }
}

extern "C" void kernel_launch(void* const* d_in, const int* in_sizes, int n_in,
                              void* d_out, int out_size) {
    const float* x      = (const float*)d_in[0];  // [16384, 4096]
    const float* logits = (const float*)d_in[1];  // [16384, 64]
    float* out = (float*)d_out;

    const size_t expanded_elems = (size_t)BATCH * TOP_K * DIM;
    float* idx_out = out + expanded_elems;
    float* w_out   = idx_out + (size_t)BATCH * TOP_K;

    const unsigned total_f4 = (unsigned)BATCH * (DIM / 4);  // 16,777,216
    const unsigned blocks = total_f4 / 256;                  // 65,536
    fused_dispatch_kernel<<<blocks, 256>>>((const float4*)x, logits,
                                           (float4*)out, idx_out, w_out);
}